// round 1
// baseline (speedup 1.0000x reference)
#include <cuda_runtime.h>
#include <cuda_bf16.h>

#define B_  16
#define N_  512
#define E_  32
#define HD  64

// Scratch: A[b][k][n] = H[b,n,:] @ W1[:32, k]
//          Bm[b][k][n] = H[b,n,:] @ W1[32:, k] + b1[k]
__device__ float g_A[B_ * HD * N_];
__device__ float g_Bm[B_ * HD * N_];

// ---------------------------------------------------------------------------
// Kernel 1: precompute A and Bm, written k-major so the pair kernel loads
// its smem tiles fully coalesced with no transpose.
// grid = B * 8 * 2 = 256 blocks of 256 threads.
//   blockIdx.x bit0: which half (0 = A, 1 = Bm)
//   bits[1:3]: n-chunk of 64
//   bits[4:]:  batch
// ---------------------------------------------------------------------------
__global__ void __launch_bounds__(256) precompute_kernel(
    const float* __restrict__ H,
    const float* __restrict__ W1,
    const float* __restrict__ b1)
{
    int which  = blockIdx.x & 1;
    int nChunk = (blockIdx.x >> 1) & 7;
    int b      = blockIdx.x >> 4;

    __shared__ float sW[E_ * HD];     // 32x64 half of W1
    __shared__ float sH[64 * 33];     // 64 node rows, padded (+1) vs bank conflicts

    int tid = threadIdx.x;
    const float* Wsrc = W1 + which * E_ * HD;
    #pragma unroll
    for (int p = tid; p < E_ * HD; p += 256) sW[p] = Wsrc[p];

    int nBase = b * N_ + nChunk * 64;
    #pragma unroll
    for (int p = tid; p < 64 * E_; p += 256) {
        int r = p >> 5, c = p & 31;
        sH[r * 33 + c] = H[nBase * E_ + p];
    }
    __syncthreads();

    int nL    = tid & 63;
    int kBase = (tid >> 6) * 16;   // 4 groups of threads x 16 k each

    float h[E_];
    #pragma unroll
    for (int e = 0; e < E_; e++) h[e] = sH[nL * 33 + e];

    float* dst = which ? g_Bm : g_A;
    #pragma unroll
    for (int kk = 0; kk < 16; kk++) {
        int k = kBase + kk;
        float acc = which ? b1[k] : 0.0f;
        #pragma unroll
        for (int e = 0; e < E_; e++)
            acc = fmaf(h[e], sW[e * HD + k], acc);   // sW read: warp-uniform k -> broadcast
        dst[(b * HD + k) * N_ + nChunk * 64 + nL] = acc;   // coalesced (n fastest)
    }
}

// ---------------------------------------------------------------------------
// Kernel 2: pair MLP over 64x64 (i,j) tiles of the upper triangle.
// grid = (36 upper-tri tiles, 16 batches), 256 threads.
// Thread (ty, tx) computes a 4x4 register tile:
//   logit(i,j) = b2 + sum_k relu(A[i][k] + Bm[j][k]) * W2[k]
//   adj[i][j] = adj[j][i] = sigmoid(logit)
// ---------------------------------------------------------------------------
__global__ void __launch_bounds__(256) pair_kernel(
    const float* __restrict__ W2,
    const float* __restrict__ b2,
    float* __restrict__ out)
{
    int b = blockIdx.y;
    int t = blockIdx.x;
    int ti = 0;
    while (t >= (8 - ti)) { t -= (8 - ti); ti++; }
    int tj = ti + t;    // ti <= tj

    __shared__ float4 As[HD * 16];   // [k][i4]  (i4 = 4-float group of i-local)
    __shared__ float4 Bs[HD * 16];   // [k][j4]
    __shared__ float  sw2[HD];
    __shared__ float  sb2;

    int tid = threadIdx.x;
    const float4* Ag = reinterpret_cast<const float4*>(g_A  + (size_t)b * HD * N_ + ti * 64);
    const float4* Bg = reinterpret_cast<const float4*>(g_Bm + (size_t)b * HD * N_ + tj * 64);

    #pragma unroll
    for (int p = 0; p < 4; p++) {
        int idx = tid + p * 256;        // 0..1023
        int k = idx >> 4, v4 = idx & 15;
        As[idx] = Ag[k * (N_ / 4) + v4];   // coalesced: 16 float4 per k-row
        Bs[idx] = Bg[k * (N_ / 4) + v4];
    }
    if (tid < HD) sw2[tid] = W2[tid];
    if (tid == 0) sb2 = b2[0];
    __syncthreads();

    int ty = tid >> 4, tx = tid & 15;

    float acc[4][4];
    float bb = sb2;
    #pragma unroll
    for (int r = 0; r < 4; r++)
        #pragma unroll
        for (int c = 0; c < 4; c++) acc[r][c] = bb;

    #pragma unroll 16
    for (int k = 0; k < HD; k++) {
        float4 a  = As[k * 16 + ty];
        float4 bv = Bs[k * 16 + tx];
        float  w  = sw2[k];
        float ar[4] = {a.x, a.y, a.z, a.w};
        float br[4] = {bv.x, bv.y, bv.z, bv.w};
        #pragma unroll
        for (int r = 0; r < 4; r++)
            #pragma unroll
            for (int c = 0; c < 4; c++) {
                float tv = fmaxf(ar[r] + br[c], 0.0f);
                acc[r][c] = fmaf(tv, w, acc[r][c]);
            }
    }

    float p[4][4];
    #pragma unroll
    for (int r = 0; r < 4; r++)
        #pragma unroll
        for (int c = 0; c < 4; c++)
            p[r][c] = 1.0f / (1.0f + __expf(-acc[r][c]));

    int i0 = ti * 64 + ty * 4;
    int j0 = tj * 64 + tx * 4;
    float* outb = out + (size_t)b * N_ * N_;

    if (ti != tj) {
        // all i < j: write tile and its mirror, both float4-vectorized
        #pragma unroll
        for (int r = 0; r < 4; r++) {
            float4 v = make_float4(p[r][0], p[r][1], p[r][2], p[r][3]);
            *reinterpret_cast<float4*>(outb + (size_t)(i0 + r) * N_ + j0) = v;
        }
        #pragma unroll
        for (int c = 0; c < 4; c++) {
            float4 v = make_float4(p[0][c], p[1][c], p[2][c], p[3][c]);
            *reinterpret_cast<float4*>(outb + (size_t)(j0 + c) * N_ + i0) = v;
        }
    } else {
        // diagonal tile: i<j writes both, i==j writes 0, i>j mirrored by i<j
        #pragma unroll
        for (int r = 0; r < 4; r++)
            #pragma unroll
            for (int c = 0; c < 4; c++) {
                int i = i0 + r, j = j0 + c;
                if (i < j) {
                    float v = p[r][c];
                    outb[(size_t)i * N_ + j] = v;
                    outb[(size_t)j * N_ + i] = v;
                } else if (i == j) {
                    outb[(size_t)i * N_ + j] = 0.0f;
                }
            }
    }
}

extern "C" void kernel_launch(void* const* d_in, const int* in_sizes, int n_in,
                              void* d_out, int out_size)
{
    const float* H  = (const float*)d_in[0];   // node_emb [8192, 32]
    const float* W1 = (const float*)d_in[1];   // [64, 64]
    const float* b1 = (const float*)d_in[2];   // [64]
    const float* W2 = (const float*)d_in[3];   // [64]
    const float* b2 = (const float*)d_in[4];   // [1]
    float* out = (float*)d_out;                // [16, 512, 512]

    precompute_kernel<<<256, 256>>>(H, W1, b1);
    pair_kernel<<<dim3(36, 16), 256>>>(W2, b2, out);
}

// round 2
// speedup vs baseline: 1.0234x; 1.0234x over previous
#include <cuda_runtime.h>
#include <cuda_bf16.h>

#define B_  16
#define N_  512
#define E_  32
#define HD  64

// Scratch: A[b][k][n] = H[b,n,:] @ W1[:32, k]
//          Bm[b][k][n] = H[b,n,:] @ W1[32:, k] + b1[k]
__device__ float g_A[B_ * HD * N_];
__device__ float g_Bm[B_ * HD * N_];

__constant__ float c_W2[HD];
__constant__ float c_b2;

// ---------------------------------------------------------------------------
// Kernel 1: precompute A and Bm, written k-major so the pair kernel loads
// its smem tiles fully coalesced with no transpose.
// ---------------------------------------------------------------------------
__global__ void __launch_bounds__(256) precompute_kernel(
    const float* __restrict__ H,
    const float* __restrict__ W1,
    const float* __restrict__ b1)
{
    int which  = blockIdx.x & 1;
    int nChunk = (blockIdx.x >> 1) & 7;
    int b      = blockIdx.x >> 4;

    __shared__ float sW[E_ * HD];
    __shared__ float sH[64 * 33];

    int tid = threadIdx.x;
    const float* Wsrc = W1 + which * E_ * HD;
    #pragma unroll
    for (int p = tid; p < E_ * HD; p += 256) sW[p] = Wsrc[p];

    int nBase = b * N_ + nChunk * 64;
    #pragma unroll
    for (int p = tid; p < 64 * E_; p += 256) {
        int r = p >> 5, c = p & 31;
        sH[r * 33 + c] = H[nBase * E_ + p];
    }
    __syncthreads();

    int nL    = tid & 63;
    int kBase = (tid >> 6) * 16;

    float h[E_];
    #pragma unroll
    for (int e = 0; e < E_; e++) h[e] = sH[nL * 33 + e];

    float* dst = which ? g_Bm : g_A;
    #pragma unroll
    for (int kk = 0; kk < 16; kk++) {
        int k = kBase + kk;
        float acc = which ? b1[k] : 0.0f;
        #pragma unroll
        for (int e = 0; e < E_; e++)
            acc = fmaf(h[e], sW[e * HD + k], acc);
        dst[(b * HD + k) * N_ + nChunk * 64 + nL] = acc;
    }
}

// ---------------------------------------------------------------------------
// packed f32x2 inner step:
//   (t0,t1) = a2 + b2;  relu each half;  acc2 += (t0,t1) * w2
// fma pipe: ADD2 + FFMA2 (2 ops / 2 elements); alu pipe: 2x FMNMX.
// ---------------------------------------------------------------------------
__device__ __forceinline__ void pair_step(unsigned long long& acc,
                                          unsigned long long a2,
                                          unsigned long long b2,
                                          unsigned long long w2)
{
    asm("{\n\t"
        ".reg .f32 lo, hi;\n\t"
        ".reg .b64 t, r;\n\t"
        "add.rn.f32x2 t, %1, %2;\n\t"
        "mov.b64 {lo, hi}, t;\n\t"
        "max.f32 lo, lo, 0f00000000;\n\t"
        "max.f32 hi, hi, 0f00000000;\n\t"
        "mov.b64 r, {lo, hi};\n\t"
        "fma.rn.f32x2 %0, r, %3, %0;\n\t"
        "}"
        : "+l"(acc) : "l"(a2), "l"(b2), "l"(w2));
}

__device__ __forceinline__ unsigned long long dup_f32(float x)
{
    unsigned long long d;
    asm("mov.b64 %0, {%1, %1};" : "=l"(d) : "f"(x));
    return d;
}

// ---------------------------------------------------------------------------
// Kernel 2: pair MLP over 64x64 (i,j) tiles of the upper triangle.
// grid = (36, 16), 256 threads. Thread (ty,tx): 4 rows x 4 cols (= 8 f32x2 pairs).
//   As_dup[k][i]  : (a,a) duplicated   -> broadcast LDS.64, no packing MOVs
//   Bs2[k][pos]   : natural (b_j,b_j+1) pairs, interleaved layout so each
//                   LDS.64 is a conflict-free stride-8B access
// smem = 32KB + 16KB = 48KB exactly -> 4 blocks/SM -> 576 blocks = 1 wave.
// ---------------------------------------------------------------------------
__global__ void __launch_bounds__(256) pair_kernel(float* __restrict__ out)
{
    int b = blockIdx.y;
    int t = blockIdx.x;
    int ti = 0;
    while (t >= (8 - ti)) { t -= (8 - ti); ti++; }
    int tj = ti + t;    // ti <= tj

    __shared__ unsigned long long As_dup[HD * 64];  // 32 KB
    __shared__ unsigned long long Bs2[HD * 32];     // 16 KB

    int tid = threadIdx.x;

    // Fill As_dup: each element duplicated (a,a)
    const float* Ag = g_A + (size_t)b * HD * N_ + ti * 64;
    #pragma unroll
    for (int p = 0; p < 16; p++) {
        int idx = tid + p * 256;          // 0..4095
        int k = idx >> 6, i = idx & 63;
        As_dup[idx] = dup_f32(Ag[k * N_ + i]);
    }

    // Fill Bs2: natural adjacent-j pairs, interleaved so tx-strided reads are
    // contiguous 8B: pair jp stored at (jp&1)*16 + (jp>>1)
    const float2* Bg = reinterpret_cast<const float2*>(g_Bm + (size_t)b * HD * N_ + tj * 64);
    #pragma unroll
    for (int p = 0; p < 8; p++) {
        int idx = tid + p * 256;          // 0..2047
        int k = idx >> 5, jp = idx & 31;
        float2 v = Bg[k * (N_ / 2) + jp];
        int pos = ((jp & 1) << 4) | (jp >> 1);
        Bs2[(k << 5) + pos] = *reinterpret_cast<unsigned long long*>(&v);
    }
    __syncthreads();

    int ty = tid >> 4, tx = tid & 15;

    unsigned long long acc[4][2];
    {
        unsigned long long ai = dup_f32(c_b2);
        #pragma unroll
        for (int r = 0; r < 4; r++) { acc[r][0] = ai; acc[r][1] = ai; }
    }

    #pragma unroll 8
    for (int k = 0; k < HD; k++) {
        unsigned long long w2 = dup_f32(c_W2[k]);
        unsigned long long b0 = Bs2[(k << 5) + tx];        // cols (4tx, 4tx+1)
        unsigned long long b1v = Bs2[(k << 5) + 16 + tx];  // cols (4tx+2, 4tx+3)
        const unsigned long long* Ak = &As_dup[(k << 6) + (ty << 2)];
        #pragma unroll
        for (int r = 0; r < 4; r++) {
            unsigned long long a2 = Ak[r];
            pair_step(acc[r][0], a2, b0, w2);
            pair_step(acc[r][1], a2, b1v, w2);
        }
    }

    // sigmoid epilogue
    float p[4][4];
    #pragma unroll
    for (int r = 0; r < 4; r++)
        #pragma unroll
        for (int cp = 0; cp < 2; cp++) {
            float lo, hi;
            asm("mov.b64 {%0, %1}, %2;" : "=f"(lo), "=f"(hi) : "l"(acc[r][cp]));
            p[r][cp * 2 + 0] = 1.0f / (1.0f + __expf(-lo));
            p[r][cp * 2 + 1] = 1.0f / (1.0f + __expf(-hi));
        }

    int i0 = ti * 64 + ty * 4;
    int j0 = tj * 64 + tx * 4;
    float* outb = out + (size_t)b * N_ * N_;

    if (ti != tj) {
        #pragma unroll
        for (int r = 0; r < 4; r++) {
            float4 v = make_float4(p[r][0], p[r][1], p[r][2], p[r][3]);
            *reinterpret_cast<float4*>(outb + (size_t)(i0 + r) * N_ + j0) = v;
        }
        #pragma unroll
        for (int c = 0; c < 4; c++) {
            float4 v = make_float4(p[0][c], p[1][c], p[2][c], p[3][c]);
            *reinterpret_cast<float4*>(outb + (size_t)(j0 + c) * N_ + i0) = v;
        }
    } else {
        #pragma unroll
        for (int r = 0; r < 4; r++)
            #pragma unroll
            for (int c = 0; c < 4; c++) {
                int i = i0 + r, j = j0 + c;
                if (i < j) {
                    float v = p[r][c];
                    outb[(size_t)i * N_ + j] = v;
                    outb[(size_t)j * N_ + i] = v;
                } else if (i == j) {
                    outb[(size_t)i * N_ + j] = 0.0f;
                }
            }
    }
}

extern "C" void kernel_launch(void* const* d_in, const int* in_sizes, int n_in,
                              void* d_out, int out_size)
{
    const float* H  = (const float*)d_in[0];   // node_emb [8192, 32]
    const float* W1 = (const float*)d_in[1];   // [64, 64]
    const float* b1 = (const float*)d_in[2];   // [64]
    const float* W2 = (const float*)d_in[3];   // [64]
    const float* b2 = (const float*)d_in[4];   // [1]
    float* out = (float*)d_out;                // [16, 512, 512]

    // Stage tiny weights into constant memory (D2D, graph-capturable)
    cudaMemcpyToSymbolAsync(c_W2, W2, HD * sizeof(float), 0, cudaMemcpyDeviceToDevice);
    cudaMemcpyToSymbolAsync(c_b2, b2, sizeof(float), 0, cudaMemcpyDeviceToDevice);

    precompute_kernel<<<256, 256>>>(H, W1, b1);
    pair_kernel<<<dim3(36, 16), 256>>>(out);
}

// round 4
// speedup vs baseline: 1.0446x; 1.0207x over previous
#include <cuda_runtime.h>
#include <cuda_bf16.h>

#define B_  16
#define N_  512
#define E_  32
#define HD  64

// Scratch: A[b][k][n] = H[b,n,:] @ W1[:32, k]
//          Bm[b][k][n] = H[b,n,:] @ W1[32:, k] + b1[k]
__device__ float g_A[B_ * HD * N_];
__device__ float g_Bm[B_ * HD * N_];

// ---------------------------------------------------------------------------
// Kernel 1: precompute A and Bm, written k-major so the pair kernel loads
// its smem tiles fully coalesced with no transpose.
// ---------------------------------------------------------------------------
__global__ void __launch_bounds__(256) precompute_kernel(
    const float* __restrict__ H,
    const float* __restrict__ W1,
    const float* __restrict__ b1)
{
    int which  = blockIdx.x & 1;
    int nChunk = (blockIdx.x >> 1) & 7;
    int b      = blockIdx.x >> 4;

    __shared__ float sW[E_ * HD];
    __shared__ float sH[64 * 33];

    int tid = threadIdx.x;
    const float* Wsrc = W1 + which * E_ * HD;
    #pragma unroll
    for (int p = tid; p < E_ * HD; p += 256) sW[p] = Wsrc[p];

    int nBase = b * N_ + nChunk * 64;
    #pragma unroll
    for (int p = tid; p < 64 * E_; p += 256) {
        int r = p >> 5, c = p & 31;
        sH[r * 33 + c] = H[nBase * E_ + p];
    }
    __syncthreads();

    int nL    = tid & 63;
    int kBase = (tid >> 6) * 16;

    float h[E_];
    #pragma unroll
    for (int e = 0; e < E_; e++) h[e] = sH[nL * 33 + e];

    float* dst = which ? g_Bm : g_A;
    #pragma unroll
    for (int kk = 0; kk < 16; kk++) {
        int k = kBase + kk;
        float acc = which ? b1[k] : 0.0f;
        #pragma unroll
        for (int e = 0; e < E_; e++)
            acc = fmaf(h[e], sW[e * HD + k], acc);
        dst[(b * HD + k) * N_ + nChunk * 64 + nL] = acc;
    }

    // PDL: signal dependent pair_kernel that our output is committed.
    cudaTriggerProgrammaticLaunchCompletion();
}

// ---------------------------------------------------------------------------
// packed f32x2 inner step:
//   t = a2 + b2 (ADD2, fma pipe); relu halves (2x FMNMX, alu pipe);
//   acc += t * w2 (FFMA2, fma pipe)
// ---------------------------------------------------------------------------
__device__ __forceinline__ void pair_step(unsigned long long& acc,
                                          unsigned long long a2,
                                          unsigned long long b2,
                                          unsigned long long w2)
{
    asm("{\n\t"
        ".reg .f32 lo, hi;\n\t"
        ".reg .b64 t, r;\n\t"
        "add.rn.f32x2 t, %1, %2;\n\t"
        "mov.b64 {lo, hi}, t;\n\t"
        "max.f32 lo, lo, 0f00000000;\n\t"
        "max.f32 hi, hi, 0f00000000;\n\t"
        "mov.b64 r, {lo, hi};\n\t"
        "fma.rn.f32x2 %0, r, %3, %0;\n\t"
        "}"
        : "+l"(acc) : "l"(a2), "l"(b2), "l"(w2));
}

__device__ __forceinline__ unsigned long long dup_f32(float x)
{
    unsigned long long d;
    asm("mov.b64 %0, {%1, %1};" : "=l"(d) : "f"(x));
    return d;
}

// ---------------------------------------------------------------------------
// Kernel 2: pair MLP over 64x64 (i,j) tiles of the upper triangle.
// grid = (36, 16), 256 threads. Thread (ty,tx): 4 rows x 4 cols.
//   As_dup[k][i] : (a,a) duplicated -> 2x LDS.128 per k give 4 aligned pairs
//   Bs4[k][q]    : natural float4   -> 1x LDS.128 per k gives 2 packed pairs
//   sw2d[k]      : duplicated W2    -> 1x LDS.64 broadcast per k
// All inner-loop LDS use compile-time immediate offsets (full unroll by 16).
// smem = 32KB + 16KB + ~0.6KB -> 4 blocks/SM -> 576 blocks = single wave.
// ---------------------------------------------------------------------------
__global__ void __launch_bounds__(256) pair_kernel(
    const float* __restrict__ W2,
    const float* __restrict__ b2g,
    float* __restrict__ out)
{
    __shared__ alignas(16) unsigned long long As_dup[HD * 64];  // 32 KB
    __shared__ alignas(16) float4             Bs4[HD * 16];     // 16 KB
    __shared__ unsigned long long sw2d[HD];
    __shared__ float sb2;

    int tid = threadIdx.x;

    // Prolog that does NOT depend on precompute output (overlaps via PDL)
    if (tid < HD) sw2d[tid] = dup_f32(W2[tid]);
    if (tid == 0) sb2 = b2g[0];

    int b = blockIdx.y;
    int t = blockIdx.x;
    int ti = 0;
    while (t >= (8 - ti)) { t -= (8 - ti); ti++; }
    int tj = ti + t;    // ti <= tj

    // Wait for precompute's g_A / g_Bm to be visible
    cudaGridDependencySynchronize();

    // Fill As_dup: LDG.128 + duplicate + 2x STS.128 per float4
    const float4* Ag4 = reinterpret_cast<const float4*>(g_A + (size_t)b * HD * N_ + ti * 64);
    #pragma unroll
    for (int p = 0; p < 4; p++) {
        int idx = tid + p * 256;          // 0..1023 float4 slots
        int k = idx >> 4, q = idx & 15;
        float4 v = Ag4[k * (N_ / 4) + q];
        ulonglong2* dst = reinterpret_cast<ulonglong2*>(&As_dup[(k << 6) + (q << 2)]);
        dst[0] = make_ulonglong2(dup_f32(v.x), dup_f32(v.y));
        dst[1] = make_ulonglong2(dup_f32(v.z), dup_f32(v.w));
    }

    // Fill Bs4: straight float4 copy
    const float4* Bg4 = reinterpret_cast<const float4*>(g_Bm + (size_t)b * HD * N_ + tj * 64);
    #pragma unroll
    for (int p = 0; p < 4; p++) {
        int idx = tid + p * 256;
        int k = idx >> 4, q = idx & 15;
        Bs4[(k << 4) + q] = Bg4[k * (N_ / 4) + q];
    }
    __syncthreads();

    int ty = tid >> 4, tx = tid & 15;

    unsigned long long acc[4][2];
    {
        unsigned long long bi = dup_f32(sb2);
        #pragma unroll
        for (int r = 0; r < 4; r++) { acc[r][0] = bi; acc[r][1] = bi; }
    }

    const unsigned long long* Ap = As_dup + (ty << 2);
    const ulonglong2*         Bp = reinterpret_cast<const ulonglong2*>(Bs4 + tx);

    #pragma unroll 16
    for (int k = 0; k < HD; k++) {
        unsigned long long w2 = sw2d[k];                                  // LDS.64 bcast
        ulonglong2 bv  = Bp[k << 4];                                      // LDS.128: pairs (b0,b1),(b2,b3); row stride = 16 ulonglong2
        ulonglong2 a01 = *reinterpret_cast<const ulonglong2*>(Ap + (k << 6));      // (a0,a0),(a1,a1)
        ulonglong2 a23 = *reinterpret_cast<const ulonglong2*>(Ap + (k << 6) + 2);  // (a2,a2),(a3,a3)
        pair_step(acc[0][0], a01.x, bv.x, w2);
        pair_step(acc[0][1], a01.x, bv.y, w2);
        pair_step(acc[1][0], a01.y, bv.x, w2);
        pair_step(acc[1][1], a01.y, bv.y, w2);
        pair_step(acc[2][0], a23.x, bv.x, w2);
        pair_step(acc[2][1], a23.x, bv.y, w2);
        pair_step(acc[3][0], a23.y, bv.x, w2);
        pair_step(acc[3][1], a23.y, bv.y, w2);
    }

    // sigmoid epilogue
    float p[4][4];
    #pragma unroll
    for (int r = 0; r < 4; r++)
        #pragma unroll
        for (int cp = 0; cp < 2; cp++) {
            float lo, hi;
            asm("mov.b64 {%0, %1}, %2;" : "=f"(lo), "=f"(hi) : "l"(acc[r][cp]));
            p[r][cp * 2 + 0] = 1.0f / (1.0f + __expf(-lo));
            p[r][cp * 2 + 1] = 1.0f / (1.0f + __expf(-hi));
        }

    int i0 = ti * 64 + ty * 4;
    int j0 = tj * 64 + tx * 4;
    float* outb = out + (size_t)b * N_ * N_;

    if (ti != tj) {
        #pragma unroll
        for (int r = 0; r < 4; r++) {
            float4 v = make_float4(p[r][0], p[r][1], p[r][2], p[r][3]);
            *reinterpret_cast<float4*>(outb + (size_t)(i0 + r) * N_ + j0) = v;
        }
        #pragma unroll
        for (int c = 0; c < 4; c++) {
            float4 v = make_float4(p[0][c], p[1][c], p[2][c], p[3][c]);
            *reinterpret_cast<float4*>(outb + (size_t)(j0 + c) * N_ + i0) = v;
        }
    } else {
        #pragma unroll
        for (int r = 0; r < 4; r++)
            #pragma unroll
            for (int c = 0; c < 4; c++) {
                int i = i0 + r, j = j0 + c;
                if (i < j) {
                    float v = p[r][c];
                    outb[(size_t)i * N_ + j] = v;
                    outb[(size_t)j * N_ + i] = v;
                } else if (i == j) {
                    outb[(size_t)i * N_ + j] = 0.0f;
                }
            }
    }
}

extern "C" void kernel_launch(void* const* d_in, const int* in_sizes, int n_in,
                              void* d_out, int out_size)
{
    const float* H  = (const float*)d_in[0];   // node_emb [8192, 32]
    const float* W1 = (const float*)d_in[1];   // [64, 64]
    const float* b1 = (const float*)d_in[2];   // [64]
    const float* W2 = (const float*)d_in[3];   // [64]
    const float* b2 = (const float*)d_in[4];   // [1]
    float* out = (float*)d_out;                // [16, 512, 512]

    precompute_kernel<<<256, 256>>>(H, W1, b1);

    // PDL launch: pair_kernel's prolog overlaps precompute tail + launch gap
    cudaLaunchConfig_t cfg = {};
    cfg.gridDim  = dim3(36, 16, 1);
    cfg.blockDim = dim3(256, 1, 1);
    cfg.dynamicSmemBytes = 0;
    cfg.stream = 0;
    cudaLaunchAttribute attrs[1];
    attrs[0].id = cudaLaunchAttributeProgrammaticStreamSerialization;
    attrs[0].val.programmaticStreamSerializationAllowed = 1;
    cfg.attrs = attrs;
    cfg.numAttrs = 1;
    cudaLaunchKernelEx(&cfg, pair_kernel, W2, b2, out);
}